// round 17
// baseline (speedup 1.0000x reference)
#include <cuda_runtime.h>

#define BATCH 4
#define NPTS  8192
#define MPTS  8192
#define KSEL  16
#define KBUF  18
#define TILE  2048
#define SRCB  64                // src points per block
#define PARTS 4                 // dst-dimension split per src point
#define TPB   (SRCB * PARTS)    // 256
#define JSEG  (TILE / PARTS)    // 512 candidates per thread per tile

// Shared memory: tile buffer and candidate buffers are live in disjoint
// phases -> union them.
union SmemU {
    float4 tile[TILE];                       // 32 KB (staging + hot loop)
    struct {
        float cd[PARTS][SRCB][KBUF];         // 18 KB
        int   ci[PARTS][SRCB][KBUF];         // 18 KB
    } cand;                                  // 36 KB (merge phase)
};

__global__ __launch_bounds__(TPB, 3) void knn_kernel(
    const float* __restrict__ src,
    const float* __restrict__ dst,
    float* __restrict__ out,
    int write_idx)
{
    __shared__ SmemU sm;

    const int s_lane = threadIdx.x & (SRCB - 1);   // src lane within block
    const int part   = threadIdx.x >> 6;           // dst slice [part*512, ...)

    const int blocks_per_batch = NPTS / SRCB;      // 128
    const int b = blockIdx.x / blocks_per_batch;
    const int n = (blockIdx.x % blocks_per_batch) * SRCB + s_lane;

    const float* sp = src + ((long)b * NPTS + n) * 3;
    const float sx = sp[0];
    const float sy = sp[1];
    const float sz = sp[2];

    // sq_src = S_L (ordering-neutral site; validated config)
    const float sq_s = __fadd_rn(__fadd_rn(__fmul_rn(sx, sx), __fmul_rn(sy, sy)),
                                 __fmul_rn(sz, sz));

    // Per-thread sorted-ascending top-KBUF by d2 over this thread's dst slice.
    float bd[KBUF];
    int   bi[KBUF];
#pragma unroll
    for (int t = 0; t < KBUF; ++t) { bd[t] = 3.402823e38f; bi[t] = 0; }
    float worst = 3.402823e38f;

    const float* dbase = dst + (long)b * MPTS * 3;

    for (int tile = 0; tile < MPTS; tile += TILE) {
        // Cooperative stage (256 threads, 8 float4 each)
        for (int i = threadIdx.x; i < TILE; i += TPB) {
            const float* dp = dbase + (long)(tile + i) * 3;
            const float y0 = dp[0], y1 = dp[1], y2 = dp[2];
            // sq_dst = S_R: y0^2 + (y1^2 + y2^2)  (validated config)
            const float sq_d = __fadd_rn(
                __fmul_rn(y0, y0),
                __fadd_rn(__fmul_rn(y1, y1), __fmul_rn(y2, y2)));
            sm.tile[i] = make_float4(y0, y1, y2, sq_d);
        }
        __syncthreads();

        const int jbase = part * JSEG;
#pragma unroll 8
        for (int j = 0; j < JSEG; ++j) {
            const float4 p = sm.tile[jbase + j];   // warp-uniform broadcast

            // inner = I_C: fma(x2,y2, fma(x1,y1, rn(x0*y0)))  (validated)
            const float inner =
                __fmaf_rn(sz, p.z, __fmaf_rn(sy, p.y, __fmul_rn(sx, p.x)));

            // combine = split1: d2 = s + rn(d - 2*inner)  (validated)
            const float d2 =
                __fadd_rn(sq_s, __fmaf_rn(-2.0f, inner, p.w));

            if (d2 < worst) {
                float cv = d2;
                int   ci = tile + jbase + j;
#pragma unroll
                for (int t = 0; t < KBUF; ++t) {
                    const bool lt = cv < bd[t];
                    const float tf = bd[t]; const int ti = bi[t];
                    if (lt) { bd[t] = cv; bi[t] = ci; cv = tf; ci = ti; }
                }
                worst = bd[KBUF - 1];
            }
        }
        __syncthreads();
    }

    // Publish per-part candidates to shared.
#pragma unroll
    for (int t = 0; t < KBUF; ++t) {
        sm.cand.cd[part][s_lane][t] = bd[t];
        sm.cand.ci[part][s_lane][t] = bi[t];
    }
    __syncthreads();

    // Merge (one thread per src point: part 0 threads).
    if (part == 0) {
        int kp[PARTS] = {0, 0, 0, 0};
        float fd[KBUF];
        int   fi[KBUF];

        // 4-way merge of sorted-by-d2 lists; exact d2 compare, lower index
        // wins ties (identical semantics to a single ascending-j scan).
#pragma unroll
        for (int o = 0; o < KBUF; ++o) {
            int   bp = 0;
            float bv = sm.cand.cd[0][s_lane][kp[0]];
            int   bx = sm.cand.ci[0][s_lane][kp[0]];
#pragma unroll
            for (int p2 = 1; p2 < PARTS; ++p2) {
                const float v = sm.cand.cd[p2][s_lane][kp[p2]];
                const int   x = sm.cand.ci[p2][s_lane][kp[p2]];
                if (v < bv || (v == bv && x < bx)) { bp = p2; bv = v; bx = x; }
            }
            fd[o] = bv; fi[o] = bx; kp[bp]++;
        }

        // sqrt + (dist, index) stable rerank (validated epilogue).
        float dd[KBUF];
#pragma unroll
        for (int t = 0; t < KBUF; ++t)
            dd[t] = __fsqrt_rn(fmaxf(fd[t], 0.0f));

#pragma unroll
        for (int a = 0; a < KBUF - 1; ++a) {
#pragma unroll
            for (int q = 0; q < KBUF - 1 - a; ++q) {
                const bool sw = (dd[q + 1] < dd[q]) ||
                                (dd[q + 1] == dd[q] && fi[q + 1] < fi[q]);
                if (sw) {
                    const float tf = dd[q]; dd[q] = dd[q + 1]; dd[q + 1] = tf;
                    const int   ti = fi[q]; fi[q] = fi[q + 1]; fi[q + 1] = ti;
                }
            }
        }

        const long base = ((long)b * NPTS + n) * KSEL;
        float* dist_out = out;
        float* idx_out  = out + (long)BATCH * NPTS * KSEL;
#pragma unroll
        for (int t = 0; t < KSEL; ++t) {
            dist_out[base + t] = dd[t];
            if (write_idx) idx_out[base + t] = (float)fi[t];
        }
    }
}

extern "C" void kernel_launch(void* const* d_in, const int* in_sizes, int n_in,
                              void* d_out, int out_size)
{
    const float* src = (const float*)d_in[0];
    const float* dst = (const float*)d_in[1];
    float* out = (float*)d_out;

    const int write_idx = (out_size >= 2 * BATCH * NPTS * KSEL) ? 1 : 0;

    const int grid = BATCH * (NPTS / SRCB);   // 512 blocks of 256 threads
    knn_kernel<<<grid, TPB>>>(src, dst, out, write_idx);
}